// round 4
// baseline (speedup 1.0000x reference)
#include <cuda_runtime.h>

// VolGeoNet trilinear interp: region-binned points + SMEM-tiled grid gather.
// Inputs: x [B,3] f32, grid_value [65^3,1] f32, grid_feature [65^3,256] f32.
// Output: concat(out [B,1], feat [B,256]) float, out first.

#define N_GRID 64
#define N1 65
#define W_FEAT 256
#define MAXB 262144
#define RBITS 4                 // 16 regions per axis, 4 cells per region
#define NBINS (16 * 16 * 16)    // 4096
#define ROWS_PER_REGION 125     // 5*5*5
#define SMEM_BYTES (ROWS_PER_REGION * W_FEAT * 4 + ROWS_PER_REGION * 4)

__device__ int g_hist[NBINS];
__device__ int g_binstart[NBINS];
__device__ int g_key[MAXB];
__device__ int g_rank[MAXB];
__device__ int g_sorted[MAXB];

__device__ __forceinline__ void cell_of(const float* __restrict__ x, int p,
                                        int& ix, int& iy, int& iz)
{
    const float rx = (x[p * 3 + 0] + 1.0f) * 32.0f;
    const float ry = (x[p * 3 + 1] + 1.0f) * 32.0f;
    const float rz = (x[p * 3 + 2] + 1.0f) * 32.0f;
    ix = (int)floorf(rx); ix = ix < 0 ? 0 : (ix > N_GRID - 1 ? N_GRID - 1 : ix);
    iy = (int)floorf(ry); iy = iy < 0 ? 0 : (iy > N_GRID - 1 ? N_GRID - 1 : iy);
    iz = (int)floorf(rz); iz = iz < 0 ? 0 : (iz > N_GRID - 1 ? N_GRID - 1 : iz);
}

__global__ void zero_hist_kernel()
{
    int i = blockIdx.x * blockDim.x + threadIdx.x;
    if (i < NBINS) g_hist[i] = 0;
}

__global__ void histo_kernel(const float* __restrict__ x, int B)
{
    int p = blockIdx.x * blockDim.x + threadIdx.x;
    if (p >= B) return;
    int ix, iy, iz;
    cell_of(x, p, ix, iy, iz);
    int key = ((ix >> 2) * 16 + (iy >> 2)) * 16 + (iz >> 2);
    g_key[p] = key;
    g_rank[p] = atomicAdd(&g_hist[key], 1);
}

// Single block, 1024 threads, 4 bins each -> exclusive scan over 4096 bins.
__global__ void __launch_bounds__(1024) scan_kernel()
{
    __shared__ int s[1024];
    const int t = threadIdx.x;
    const int base = t * 4;
    int local[4];
    int sum = 0;
#pragma unroll
    for (int i = 0; i < 4; i++) {
        local[i] = sum;
        sum += g_hist[base + i];
    }
    s[t] = sum;
    __syncthreads();
    for (int off = 1; off < 1024; off <<= 1) {
        int v = 0;
        if (t >= off) v = s[t - off];
        __syncthreads();
        if (t >= off) s[t] += v;
        __syncthreads();
    }
    const int prefix = (t == 0) ? 0 : s[t - 1];
#pragma unroll
    for (int i = 0; i < 4; i++)
        g_binstart[base + i] = prefix + local[i];
}

__global__ void scatter_kernel(int B)
{
    int p = blockIdx.x * blockDim.x + threadIdx.x;
    if (p >= B) return;
    g_sorted[g_binstart[g_key[p]] + g_rank[p]] = p;
}

// ──────────────────────────────────────────────────────────────────────────
// Main kernel: one CTA per region bin. Loads 5x5x5 grid rows into SMEM,
// then each warp processes one point entirely from SMEM.
__global__ void __launch_bounds__(1024) trilerp_tile_kernel(
    const float* __restrict__ x,
    const float* __restrict__ gv,
    const float* __restrict__ gf,
    float* __restrict__ out_val,   // [B]
    float* __restrict__ out_feat)  // [B, 256]
{
    extern __shared__ char smem_raw[];
    float4* s_feat = (float4*)smem_raw;                                   // [125][64]
    float*  s_gv   = (float*)(smem_raw + ROWS_PER_REGION * W_FEAT * 4);   // [125]

    const int bin = blockIdx.x;
    const int count = g_hist[bin];
    if (count == 0) return;

    const int tid = threadIdx.x;
    const int bx = bin >> 8;
    const int by = (bin >> 4) & 15;
    const int bz = bin & 15;
    const int rx0 = bx << 2, ry0 = by << 2, rz0 = bz << 2;

    // Load 125 feature rows (125*64 float4) into SMEM.
    for (int i = tid; i < ROWS_PER_REGION * 64; i += 1024) {
        const int r  = i >> 6;
        const int c4 = i & 63;
        const int lx = r / 25, rem = r - lx * 25, ly = rem / 5, lz = rem - ly * 5;
        const int grow = ((rx0 + lx) * N1 + (ry0 + ly)) * N1 + (rz0 + lz);
        s_feat[i] = __ldg((const float4*)(gf + (size_t)grow * W_FEAT) + c4);
    }
    // Load 125 grid values.
    if (tid < ROWS_PER_REGION) {
        const int lx = tid / 25, rem = tid - lx * 25, ly = rem / 5, lz = rem - ly * 5;
        s_gv[tid] = __ldg(gv + ((rx0 + lx) * N1 + (ry0 + ly)) * N1 + (rz0 + lz));
    }
    __syncthreads();

    const int wid  = tid >> 5;
    const int lane = tid & 31;
    const int start = g_binstart[bin];

    const int loffs[8] = { 0, 1, 5, 6, 25, 26, 30, 31 };   // (ox*5+oy)*5+oz

    for (int i = wid; i < count; i += 32) {
        const int p = g_sorted[start + i];

        const float px = __ldg(x + p * 3 + 0);
        const float py = __ldg(x + p * 3 + 1);
        const float pz = __ldg(x + p * 3 + 2);

        const float rx = (px + 1.0f) * 32.0f;
        const float ry = (py + 1.0f) * 32.0f;
        const float rz = (pz + 1.0f) * 32.0f;

        const bool valid = (rx >= 0.0f) && (rx <= 64.0f) &&
                           (ry >= 0.0f) && (ry <= 64.0f) &&
                           (rz >= 0.0f) && (rz <= 64.0f);
        const float vmask = valid ? 1.0f : 0.0f;

        int ix = (int)floorf(rx); ix = ix < 0 ? 0 : (ix > N_GRID - 1 ? N_GRID - 1 : ix);
        int iy = (int)floorf(ry); iy = iy < 0 ? 0 : (iy > N_GRID - 1 ? N_GRID - 1 : iy);
        int iz = (int)floorf(rz); iz = iz < 0 ? 0 : (iz > N_GRID - 1 ? N_GRID - 1 : iz);

        const float tx = rx - (float)ix;
        const float ty = ry - (float)iy;
        const float tz = rz - (float)iz;

        const float wx0 = 1.0f - tx, wy0 = 1.0f - ty, wz0 = 1.0f - tz;
        float w[8];
        w[0] = wx0 * wy0 * wz0;
        w[1] = wx0 * wy0 * tz;
        w[2] = wx0 * ty  * wz0;
        w[3] = wx0 * ty  * tz;
        w[4] = tx  * wy0 * wz0;
        w[5] = tx  * wy0 * tz;
        w[6] = tx  * ty  * wz0;
        w[7] = tx  * ty  * tz;

        const int lbase = ((ix - rx0) * 5 + (iy - ry0)) * 5 + (iz - rz0);

        // grid_value from SMEM: lanes 0..7 own a corner, butterfly-reduce.
        float gvv = 0.0f;
        if (lane < 8) gvv = w[lane] * s_gv[lbase + loffs[lane]];
        gvv += __shfl_xor_sync(0xffffffffu, gvv, 4);
        gvv += __shfl_xor_sync(0xffffffffu, gvv, 2);
        gvv += __shfl_xor_sync(0xffffffffu, gvv, 1);
        if (lane == 0) out_val[p] = gvv * vmask;

        float a0 = 0.f, a1 = 0.f, a2 = 0.f, a3 = 0.f;
        float b0 = 0.f, b1 = 0.f, b2 = 0.f, b3 = 0.f;

#pragma unroll
        for (int c = 0; c < 8; c++) {
            const float4* row = s_feat + (size_t)(lbase + loffs[c]) * 64;
            const float4 fa = row[lane];
            const float4 fb = row[lane + 32];
            const float wc = w[c];
            a0 = fmaf(wc, fa.x, a0);
            a1 = fmaf(wc, fa.y, a1);
            a2 = fmaf(wc, fa.z, a2);
            a3 = fmaf(wc, fa.w, a3);
            b0 = fmaf(wc, fb.x, b0);
            b1 = fmaf(wc, fb.y, b1);
            b2 = fmaf(wc, fb.z, b2);
            b3 = fmaf(wc, fb.w, b3);
        }

        // Streaming stores: keep grid_feature lines resident in L2.
        float4* frow = (float4*)(out_feat + (size_t)p * W_FEAT);
        __stcs(frow + lane,      make_float4(a0 * vmask, a1 * vmask, a2 * vmask, a3 * vmask));
        __stcs(frow + lane + 32, make_float4(b0 * vmask, b1 * vmask, b2 * vmask, b3 * vmask));
    }
}

// Fallback (B > MAXB): direct global-gather version.
__global__ void __launch_bounds__(256) trilerp_kernel(
    const float* __restrict__ x,
    const float* __restrict__ gv,
    const float* __restrict__ gf,
    float* __restrict__ out_val,
    float* __restrict__ out_feat,
    int B)
{
    const int p = (blockIdx.x * blockDim.x + threadIdx.x) >> 5;
    const int lane = threadIdx.x & 31;
    if (p >= B) return;

    const float px = __ldg(x + p * 3 + 0);
    const float py = __ldg(x + p * 3 + 1);
    const float pz = __ldg(x + p * 3 + 2);
    const float rx = (px + 1.0f) * 32.0f;
    const float ry = (py + 1.0f) * 32.0f;
    const float rz = (pz + 1.0f) * 32.0f;
    const bool valid = (rx >= 0.0f) && (rx <= 64.0f) && (ry >= 0.0f) &&
                       (ry <= 64.0f) && (rz >= 0.0f) && (rz <= 64.0f);
    const float vmask = valid ? 1.0f : 0.0f;
    int ix = (int)floorf(rx); ix = ix < 0 ? 0 : (ix > 63 ? 63 : ix);
    int iy = (int)floorf(ry); iy = iy < 0 ? 0 : (iy > 63 ? 63 : iy);
    int iz = (int)floorf(rz); iz = iz < 0 ? 0 : (iz > 63 ? 63 : iz);
    const float tx = rx - ix, ty = ry - iy, tz = rz - iz;
    const int base = (ix * N1 + iy) * N1 + iz;
    const float wx0 = 1.0f - tx, wy0 = 1.0f - ty, wz0 = 1.0f - tz;
    float w[8] = { wx0*wy0*wz0, wx0*wy0*tz, wx0*ty*wz0, wx0*ty*tz,
                   tx*wy0*wz0,  tx*wy0*tz,  tx*ty*wz0,  tx*ty*tz };
    const int offs[8] = { 0, 1, N1, N1+1, N1*N1, N1*N1+1, N1*N1+N1, N1*N1+N1+1 };

    float gvv = 0.0f;
    if (lane < 8) gvv = w[lane] * __ldg(gv + base + offs[lane]);
    gvv += __shfl_xor_sync(0xffffffffu, gvv, 4);
    gvv += __shfl_xor_sync(0xffffffffu, gvv, 2);
    gvv += __shfl_xor_sync(0xffffffffu, gvv, 1);
    if (lane == 0) out_val[p] = gvv * vmask;

    float a0=0,a1=0,a2=0,a3=0,b0=0,b1=0,b2=0,b3=0;
#pragma unroll
    for (int c = 0; c < 8; c++) {
        const float4* row = (const float4*)(gf + (size_t)(base + offs[c]) * W_FEAT);
        const float4 fa = __ldg(row + lane);
        const float4 fb = __ldg(row + lane + 32);
        const float wc = w[c];
        a0 = fmaf(wc, fa.x, a0); a1 = fmaf(wc, fa.y, a1);
        a2 = fmaf(wc, fa.z, a2); a3 = fmaf(wc, fa.w, a3);
        b0 = fmaf(wc, fb.x, b0); b1 = fmaf(wc, fb.y, b1);
        b2 = fmaf(wc, fb.z, b2); b3 = fmaf(wc, fb.w, b3);
    }
    float4* frow = (float4*)(out_feat + (size_t)p * W_FEAT);
    frow[lane]      = make_float4(a0*vmask, a1*vmask, a2*vmask, a3*vmask);
    frow[lane + 32] = make_float4(b0*vmask, b1*vmask, b2*vmask, b3*vmask);
}

extern "C" void kernel_launch(void* const* d_in, const int* in_sizes, int n_in,
                              void* d_out, int out_size)
{
    const float* x  = (const float*)d_in[0];
    const float* gv = (const float*)d_in[1];
    const float* gf = (const float*)d_in[2];
    float* out = (float*)d_out;

    const int B = in_sizes[0] / 3;
    float* out_val  = out;        // [B]
    float* out_feat = out + B;    // [B, 256]

    if (B <= MAXB) {
        static int smem_set = 0;
        if (!smem_set) {
            cudaFuncSetAttribute(trilerp_tile_kernel,
                                 cudaFuncAttributeMaxDynamicSharedMemorySize,
                                 SMEM_BYTES);
            smem_set = 1;
        }
        zero_hist_kernel<<<(NBINS + 255) / 256, 256>>>();
        histo_kernel<<<(B + 255) / 256, 256>>>(x, B);
        scan_kernel<<<1, 1024>>>();
        scatter_kernel<<<(B + 255) / 256, 256>>>(B);
        trilerp_tile_kernel<<<NBINS, 1024, SMEM_BYTES>>>(x, gv, gf, out_val, out_feat);
    } else {
        const int blocks = (B + 7) / 8;
        trilerp_kernel<<<blocks, 256>>>(x, gv, gf, out_val, out_feat, B);
    }
}

// round 5
// speedup vs baseline: 1.2696x; 1.2696x over previous
#include <cuda_runtime.h>

// VolGeoNet trilinear interp: region-binned points + SMEM-tiled gather,
// channel-split tiles (2 CTAs per region) for 3-CTA/SM occupancy and
// load/process overlap.
// Inputs: x [B,3] f32, grid_value [65^3,1] f32, grid_feature [65^3,256] f32.
// Output: concat(out [B,1], feat [B,256]) float, out first.

#define N_GRID 64
#define N1 65
#define W_FEAT 256
#define MAXB 262144
#define NBINS (16 * 16 * 16)        // 4-cell regions, 16 per axis
#define ROWS_PER_REGION 125         // 5*5*5
#define HALF_FEAT 128               // channels per CTA
// s_feat: 125 rows * 32 float4 (=128 floats) + s_gv: 125 floats (pad to 128)
#define SMEM_BYTES (ROWS_PER_REGION * HALF_FEAT * 4 + 128 * 4)

__device__ int    g_hist[NBINS];
__device__ int    g_binstart[NBINS];
__device__ int    g_key[MAXB];
__device__ int    g_rank[MAXB];
__device__ float4 g_xs[MAXB];       // sorted (x,y,z, bitcast point-index)

__global__ void zero_hist_kernel()
{
    int i = blockIdx.x * blockDim.x + threadIdx.x;
    if (i < NBINS) g_hist[i] = 0;
}

__global__ void histo_kernel(const float* __restrict__ x, int B)
{
    int p = blockIdx.x * blockDim.x + threadIdx.x;
    if (p >= B) return;
    const float rx = (x[p * 3 + 0] + 1.0f) * 32.0f;
    const float ry = (x[p * 3 + 1] + 1.0f) * 32.0f;
    const float rz = (x[p * 3 + 2] + 1.0f) * 32.0f;
    int ix = (int)floorf(rx); ix = ix < 0 ? 0 : (ix > 63 ? 63 : ix);
    int iy = (int)floorf(ry); iy = iy < 0 ? 0 : (iy > 63 ? 63 : iy);
    int iz = (int)floorf(rz); iz = iz < 0 ? 0 : (iz > 63 ? 63 : iz);
    int key = ((ix >> 2) * 16 + (iy >> 2)) * 16 + (iz >> 2);
    g_key[p] = key;
    g_rank[p] = atomicAdd(&g_hist[key], 1);
}

// Single block, 1024 threads, 4 bins each -> exclusive scan over 4096 bins.
__global__ void __launch_bounds__(1024) scan_kernel()
{
    __shared__ int s[1024];
    const int t = threadIdx.x;
    const int base = t * 4;
    int local[4];
    int sum = 0;
#pragma unroll
    for (int i = 0; i < 4; i++) {
        local[i] = sum;
        sum += g_hist[base + i];
    }
    s[t] = sum;
    __syncthreads();
    for (int off = 1; off < 1024; off <<= 1) {
        int v = 0;
        if (t >= off) v = s[t - off];
        __syncthreads();
        if (t >= off) s[t] += v;
        __syncthreads();
    }
    const int prefix = (t == 0) ? 0 : s[t - 1];
#pragma unroll
    for (int i = 0; i < 4; i++)
        g_binstart[base + i] = prefix + local[i];
}

__global__ void scatter_kernel(const float* __restrict__ x, int B)
{
    int p = blockIdx.x * blockDim.x + threadIdx.x;
    if (p >= B) return;
    const int dst = g_binstart[g_key[p]] + g_rank[p];
    g_xs[dst] = make_float4(x[p * 3 + 0], x[p * 3 + 1], x[p * 3 + 2],
                            __int_as_float(p));
}

// ──────────────────────────────────────────────────────────────────────────
// Main kernel: 2 CTAs per region bin (one per 128-channel half).
// Each CTA loads its half of the 5x5x5 tile (62.5 KB) to SMEM, then 16 warps
// each process points: lane l handles channels half*128 + 4l..4l+3.
__global__ void __launch_bounds__(512) trilerp_tile_kernel(
    const float* __restrict__ gv,
    const float* __restrict__ gf,
    float* __restrict__ out_val,   // [B]
    float* __restrict__ out_feat)  // [B, 256]
{
    extern __shared__ char smem_raw[];
    float4* s_feat = (float4*)smem_raw;                                    // [125][32]
    float*  s_gv   = (float*)(smem_raw + ROWS_PER_REGION * HALF_FEAT * 4); // [125]

    const int bin  = blockIdx.x >> 1;
    const int half = blockIdx.x & 1;
    const int count = g_hist[bin];
    if (count == 0) return;

    const int tid = threadIdx.x;
    const int bx = bin >> 8;
    const int by = (bin >> 4) & 15;
    const int bz = bin & 15;
    const int rx0 = bx << 2, ry0 = by << 2, rz0 = bz << 2;

    // Load 125 half-rows (125*32 float4) into SMEM.
#pragma unroll 2
    for (int i = tid; i < ROWS_PER_REGION * 32; i += 512) {
        const int r  = i >> 5;
        const int c4 = i & 31;
        const int lx = r / 25, rem = r - lx * 25, ly = rem / 5, lz = rem - ly * 5;
        const int grow = ((rx0 + lx) * N1 + (ry0 + ly)) * N1 + (rz0 + lz);
        s_feat[i] = __ldg((const float4*)(gf + (size_t)grow * W_FEAT) + (half << 5) + c4);
    }
    if (half == 0 && tid < ROWS_PER_REGION) {
        const int lx = tid / 25, rem = tid - lx * 25, ly = rem / 5, lz = rem - ly * 5;
        s_gv[tid] = __ldg(gv + ((rx0 + lx) * N1 + (ry0 + ly)) * N1 + (rz0 + lz));
    }
    __syncthreads();

    const int wid  = tid >> 5;
    const int lane = tid & 31;
    const int start = g_binstart[bin];

    const int loffs[8] = { 0, 1, 5, 6, 25, 26, 30, 31 };   // (ox*5+oy)*5+oz

    for (int i = wid; i < count; i += 16) {
        const float4 xp = g_xs[start + i];
        const int p = __float_as_int(xp.w);

        const float rx = (xp.x + 1.0f) * 32.0f;
        const float ry = (xp.y + 1.0f) * 32.0f;
        const float rz = (xp.z + 1.0f) * 32.0f;

        const bool valid = (rx >= 0.0f) && (rx <= 64.0f) &&
                           (ry >= 0.0f) && (ry <= 64.0f) &&
                           (rz >= 0.0f) && (rz <= 64.0f);
        const float vmask = valid ? 1.0f : 0.0f;

        int ix = (int)floorf(rx); ix = ix < 0 ? 0 : (ix > 63 ? 63 : ix);
        int iy = (int)floorf(ry); iy = iy < 0 ? 0 : (iy > 63 ? 63 : iy);
        int iz = (int)floorf(rz); iz = iz < 0 ? 0 : (iz > 63 ? 63 : iz);

        const float tx = rx - (float)ix;
        const float ty = ry - (float)iy;
        const float tz = rz - (float)iz;

        const float wx0 = 1.0f - tx, wy0 = 1.0f - ty, wz0 = 1.0f - tz;
        float w[8];
        w[0] = wx0 * wy0 * wz0;
        w[1] = wx0 * wy0 * tz;
        w[2] = wx0 * ty  * wz0;
        w[3] = wx0 * ty  * tz;
        w[4] = tx  * wy0 * wz0;
        w[5] = tx  * wy0 * tz;
        w[6] = tx  * ty  * wz0;
        w[7] = tx  * ty  * tz;

        const int lbase = ((ix - rx0) * 5 + (iy - ry0)) * 5 + (iz - rz0);

        if (half == 0) {
            // grid_value: lanes 0..7 own a corner, butterfly-reduce.
            float gvv = 0.0f;
            if (lane < 8) gvv = w[lane] * s_gv[lbase + loffs[lane]];
            gvv += __shfl_xor_sync(0xffffffffu, gvv, 4);
            gvv += __shfl_xor_sync(0xffffffffu, gvv, 2);
            gvv += __shfl_xor_sync(0xffffffffu, gvv, 1);
            if (lane == 0) out_val[p] = gvv * vmask;
        }

        float a0 = 0.f, a1 = 0.f, a2 = 0.f, a3 = 0.f;
#pragma unroll
        for (int c = 0; c < 8; c++) {
            const float4 fa = s_feat[(lbase + loffs[c]) * 32 + lane];
            const float wc = w[c];
            a0 = fmaf(wc, fa.x, a0);
            a1 = fmaf(wc, fa.y, a1);
            a2 = fmaf(wc, fa.z, a2);
            a3 = fmaf(wc, fa.w, a3);
        }

        float4* frow = (float4*)(out_feat + (size_t)p * W_FEAT);
        __stcs(frow + (half << 5) + lane,
               make_float4(a0 * vmask, a1 * vmask, a2 * vmask, a3 * vmask));
    }
}

// Fallback (B > MAXB): direct global-gather version.
__global__ void __launch_bounds__(256) trilerp_kernel(
    const float* __restrict__ x,
    const float* __restrict__ gv,
    const float* __restrict__ gf,
    float* __restrict__ out_val,
    float* __restrict__ out_feat,
    int B)
{
    const int p = (blockIdx.x * blockDim.x + threadIdx.x) >> 5;
    const int lane = threadIdx.x & 31;
    if (p >= B) return;

    const float rx = (__ldg(x + p * 3 + 0) + 1.0f) * 32.0f;
    const float ry = (__ldg(x + p * 3 + 1) + 1.0f) * 32.0f;
    const float rz = (__ldg(x + p * 3 + 2) + 1.0f) * 32.0f;
    const bool valid = (rx >= 0.0f) && (rx <= 64.0f) && (ry >= 0.0f) &&
                       (ry <= 64.0f) && (rz >= 0.0f) && (rz <= 64.0f);
    const float vmask = valid ? 1.0f : 0.0f;
    int ix = (int)floorf(rx); ix = ix < 0 ? 0 : (ix > 63 ? 63 : ix);
    int iy = (int)floorf(ry); iy = iy < 0 ? 0 : (iy > 63 ? 63 : iy);
    int iz = (int)floorf(rz); iz = iz < 0 ? 0 : (iz > 63 ? 63 : iz);
    const float tx = rx - ix, ty = ry - iy, tz = rz - iz;
    const int base = (ix * N1 + iy) * N1 + iz;
    const float wx0 = 1.0f - tx, wy0 = 1.0f - ty, wz0 = 1.0f - tz;
    float w[8] = { wx0*wy0*wz0, wx0*wy0*tz, wx0*ty*wz0, wx0*ty*tz,
                   tx*wy0*wz0,  tx*wy0*tz,  tx*ty*wz0,  tx*ty*tz };
    const int offs[8] = { 0, 1, N1, N1+1, N1*N1, N1*N1+1, N1*N1+N1, N1*N1+N1+1 };

    float gvv = 0.0f;
    if (lane < 8) gvv = w[lane] * __ldg(gv + base + offs[lane]);
    gvv += __shfl_xor_sync(0xffffffffu, gvv, 4);
    gvv += __shfl_xor_sync(0xffffffffu, gvv, 2);
    gvv += __shfl_xor_sync(0xffffffffu, gvv, 1);
    if (lane == 0) out_val[p] = gvv * vmask;

    float a0=0,a1=0,a2=0,a3=0,b0=0,b1=0,b2=0,b3=0;
#pragma unroll
    for (int c = 0; c < 8; c++) {
        const float4* row = (const float4*)(gf + (size_t)(base + offs[c]) * W_FEAT);
        const float4 fa = __ldg(row + lane);
        const float4 fb = __ldg(row + lane + 32);
        const float wc = w[c];
        a0 = fmaf(wc, fa.x, a0); a1 = fmaf(wc, fa.y, a1);
        a2 = fmaf(wc, fa.z, a2); a3 = fmaf(wc, fa.w, a3);
        b0 = fmaf(wc, fb.x, b0); b1 = fmaf(wc, fb.y, b1);
        b2 = fmaf(wc, fb.z, b2); b3 = fmaf(wc, fb.w, b3);
    }
    float4* frow = (float4*)(out_feat + (size_t)p * W_FEAT);
    frow[lane]      = make_float4(a0*vmask, a1*vmask, a2*vmask, a3*vmask);
    frow[lane + 32] = make_float4(b0*vmask, b1*vmask, b2*vmask, b3*vmask);
}

extern "C" void kernel_launch(void* const* d_in, const int* in_sizes, int n_in,
                              void* d_out, int out_size)
{
    const float* x  = (const float*)d_in[0];
    const float* gv = (const float*)d_in[1];
    const float* gf = (const float*)d_in[2];
    float* out = (float*)d_out;

    const int B = in_sizes[0] / 3;
    float* out_val  = out;        // [B]
    float* out_feat = out + B;    // [B, 256]

    if (B <= MAXB) {
        static int smem_set = 0;
        if (!smem_set) {
            cudaFuncSetAttribute(trilerp_tile_kernel,
                                 cudaFuncAttributeMaxDynamicSharedMemorySize,
                                 SMEM_BYTES);
            smem_set = 1;
        }
        zero_hist_kernel<<<(NBINS + 255) / 256, 256>>>();
        histo_kernel<<<(B + 255) / 256, 256>>>(x, B);
        scan_kernel<<<1, 1024>>>();
        scatter_kernel<<<(B + 255) / 256, 256>>>(x, B);
        trilerp_tile_kernel<<<NBINS * 2, 512, SMEM_BYTES>>>(gv, gf, out_val, out_feat);
    } else {
        const int blocks = (B + 7) / 8;
        trilerp_kernel<<<blocks, 256>>>(x, gv, gf, out_val, out_feat, B);
    }
}

// round 6
// speedup vs baseline: 1.2894x; 1.0156x over previous
#include <cuda_runtime.h>

// VolGeoNet trilinear interp: region-binned points, bin->CTA binding,
// direct L1-cached gathers (no SMEM staging, no barrier, no phase sync).
// Each region = 4^3 cells -> 5^3 = 125 grid rows; CTA handles one
// (bin, 128-channel half): working set 62.5 KB, 3 CTAs/SM -> 187.5 KB < L1.
// Inputs: x [B,3] f32, grid_value [65^3,1] f32, grid_feature [65^3,256] f32.
// Output: concat(out [B,1], feat [B,256]) float, out first.

#define N_GRID 64
#define N1 65
#define W_FEAT 256
#define MAXB 262144
#define NBINS (16 * 16 * 16)

__device__ int    g_hist[NBINS];
__device__ int    g_binstart[NBINS];
__device__ int    g_key[MAXB];
__device__ int    g_rank[MAXB];
__device__ float4 g_xs[MAXB];       // sorted (x,y,z, bitcast point-index)

__global__ void zero_hist_kernel()
{
    int i = blockIdx.x * blockDim.x + threadIdx.x;
    if (i < NBINS) g_hist[i] = 0;
}

__global__ void histo_kernel(const float* __restrict__ x, int B)
{
    int p = blockIdx.x * blockDim.x + threadIdx.x;
    if (p >= B) return;
    const float rx = (x[p * 3 + 0] + 1.0f) * 32.0f;
    const float ry = (x[p * 3 + 1] + 1.0f) * 32.0f;
    const float rz = (x[p * 3 + 2] + 1.0f) * 32.0f;
    int ix = (int)floorf(rx); ix = ix < 0 ? 0 : (ix > 63 ? 63 : ix);
    int iy = (int)floorf(ry); iy = iy < 0 ? 0 : (iy > 63 ? 63 : iy);
    int iz = (int)floorf(rz); iz = iz < 0 ? 0 : (iz > 63 ? 63 : iz);
    int key = ((ix >> 2) * 16 + (iy >> 2)) * 16 + (iz >> 2);
    g_key[p] = key;
    g_rank[p] = atomicAdd(&g_hist[key], 1);
}

// Single block, 1024 threads, 4 bins each -> exclusive scan over 4096 bins.
__global__ void __launch_bounds__(1024) scan_kernel()
{
    __shared__ int s[1024];
    const int t = threadIdx.x;
    const int base = t * 4;
    int local[4];
    int sum = 0;
#pragma unroll
    for (int i = 0; i < 4; i++) {
        local[i] = sum;
        sum += g_hist[base + i];
    }
    s[t] = sum;
    __syncthreads();
    for (int off = 1; off < 1024; off <<= 1) {
        int v = 0;
        if (t >= off) v = s[t - off];
        __syncthreads();
        if (t >= off) s[t] += v;
        __syncthreads();
    }
    const int prefix = (t == 0) ? 0 : s[t - 1];
#pragma unroll
    for (int i = 0; i < 4; i++)
        g_binstart[base + i] = prefix + local[i];
}

__global__ void scatter_kernel(const float* __restrict__ x, int B)
{
    int p = blockIdx.x * blockDim.x + threadIdx.x;
    if (p >= B) return;
    const int dst = g_binstart[g_key[p]] + g_rank[p];
    g_xs[dst] = make_float4(x[p * 3 + 0], x[p * 3 + 1], x[p * 3 + 2],
                            __int_as_float(p));
}

// ──────────────────────────────────────────────────────────────────────────
// Main kernel: 2 CTAs per region bin (one per 128-channel half), 512 threads.
// Direct global gathers; L1 captures intra-bin row reuse.
__global__ void __launch_bounds__(512) trilerp_l1_kernel(
    const float* __restrict__ gv,
    const float* __restrict__ gf,
    float* __restrict__ out_val,   // [B]
    float* __restrict__ out_feat)  // [B, 256]
{
    const int bin  = blockIdx.x >> 1;
    const int half = blockIdx.x & 1;
    const int count = g_hist[bin];
    if (count == 0) return;

    const int tid  = threadIdx.x;
    const int wid  = tid >> 5;
    const int lane = tid & 31;
    const int start = g_binstart[bin];

    const int goffs[8] = { 0, 1, N1, N1 + 1,
                           N1 * N1, N1 * N1 + 1, N1 * N1 + N1, N1 * N1 + N1 + 1 };
    const int coff = (half << 5) + lane;   // float4 column within the 1KB row

    for (int i = wid; i < count; i += 16) {
        const float4 xp = g_xs[start + i];
        const int p = __float_as_int(xp.w);

        const float rx = (xp.x + 1.0f) * 32.0f;
        const float ry = (xp.y + 1.0f) * 32.0f;
        const float rz = (xp.z + 1.0f) * 32.0f;

        const bool valid = (rx >= 0.0f) && (rx <= 64.0f) &&
                           (ry >= 0.0f) && (ry <= 64.0f) &&
                           (rz >= 0.0f) && (rz <= 64.0f);
        const float vmask = valid ? 1.0f : 0.0f;

        int ix = (int)floorf(rx); ix = ix < 0 ? 0 : (ix > 63 ? 63 : ix);
        int iy = (int)floorf(ry); iy = iy < 0 ? 0 : (iy > 63 ? 63 : iy);
        int iz = (int)floorf(rz); iz = iz < 0 ? 0 : (iz > 63 ? 63 : iz);

        const float tx = rx - (float)ix;
        const float ty = ry - (float)iy;
        const float tz = rz - (float)iz;

        const float wx0 = 1.0f - tx, wy0 = 1.0f - ty, wz0 = 1.0f - tz;
        float w[8];
        w[0] = wx0 * wy0 * wz0;
        w[1] = wx0 * wy0 * tz;
        w[2] = wx0 * ty  * wz0;
        w[3] = wx0 * ty  * tz;
        w[4] = tx  * wy0 * wz0;
        w[5] = tx  * wy0 * tz;
        w[6] = tx  * ty  * wz0;
        w[7] = tx  * ty  * tz;

        const int base = (ix * N1 + iy) * N1 + iz;

        if (half == 0) {
            float gvv = 0.0f;
            if (lane < 8) gvv = w[lane] * __ldg(gv + base + goffs[lane]);
            gvv += __shfl_xor_sync(0xffffffffu, gvv, 4);
            gvv += __shfl_xor_sync(0xffffffffu, gvv, 2);
            gvv += __shfl_xor_sync(0xffffffffu, gvv, 1);
            if (lane == 0) out_val[p] = gvv * vmask;
        }

        // 8 independent LDG.128 (L1-resident after first touch per row).
        float4 f[8];
#pragma unroll
        for (int c = 0; c < 8; c++)
            f[c] = __ldg((const float4*)(gf + (size_t)(base + goffs[c]) * W_FEAT) + coff);

        float a0 = 0.f, a1 = 0.f, a2 = 0.f, a3 = 0.f;
#pragma unroll
        for (int c = 0; c < 8; c++) {
            const float wc = w[c];
            a0 = fmaf(wc, f[c].x, a0);
            a1 = fmaf(wc, f[c].y, a1);
            a2 = fmaf(wc, f[c].z, a2);
            a3 = fmaf(wc, f[c].w, a3);
        }

        // Streaming store: don't pollute L1/L2 with output lines.
        float4* frow = (float4*)(out_feat + (size_t)p * W_FEAT);
        __stcs(frow + coff,
               make_float4(a0 * vmask, a1 * vmask, a2 * vmask, a3 * vmask));
    }
}

// Fallback (B > MAXB): direct global-gather version, unsorted.
__global__ void __launch_bounds__(256) trilerp_kernel(
    const float* __restrict__ x,
    const float* __restrict__ gv,
    const float* __restrict__ gf,
    float* __restrict__ out_val,
    float* __restrict__ out_feat,
    int B)
{
    const int p = (blockIdx.x * blockDim.x + threadIdx.x) >> 5;
    const int lane = threadIdx.x & 31;
    if (p >= B) return;

    const float rx = (__ldg(x + p * 3 + 0) + 1.0f) * 32.0f;
    const float ry = (__ldg(x + p * 3 + 1) + 1.0f) * 32.0f;
    const float rz = (__ldg(x + p * 3 + 2) + 1.0f) * 32.0f;
    const bool valid = (rx >= 0.0f) && (rx <= 64.0f) && (ry >= 0.0f) &&
                       (ry <= 64.0f) && (rz >= 0.0f) && (rz <= 64.0f);
    const float vmask = valid ? 1.0f : 0.0f;
    int ix = (int)floorf(rx); ix = ix < 0 ? 0 : (ix > 63 ? 63 : ix);
    int iy = (int)floorf(ry); iy = iy < 0 ? 0 : (iy > 63 ? 63 : iy);
    int iz = (int)floorf(rz); iz = iz < 0 ? 0 : (iz > 63 ? 63 : iz);
    const float tx = rx - ix, ty = ry - iy, tz = rz - iz;
    const int base = (ix * N1 + iy) * N1 + iz;
    const float wx0 = 1.0f - tx, wy0 = 1.0f - ty, wz0 = 1.0f - tz;
    float w[8] = { wx0*wy0*wz0, wx0*wy0*tz, wx0*ty*wz0, wx0*ty*tz,
                   tx*wy0*wz0,  tx*wy0*tz,  tx*ty*wz0,  tx*ty*tz };
    const int offs[8] = { 0, 1, N1, N1+1, N1*N1, N1*N1+1, N1*N1+N1, N1*N1+N1+1 };

    float gvv = 0.0f;
    if (lane < 8) gvv = w[lane] * __ldg(gv + base + offs[lane]);
    gvv += __shfl_xor_sync(0xffffffffu, gvv, 4);
    gvv += __shfl_xor_sync(0xffffffffu, gvv, 2);
    gvv += __shfl_xor_sync(0xffffffffu, gvv, 1);
    if (lane == 0) out_val[p] = gvv * vmask;

    float a0=0,a1=0,a2=0,a3=0,b0=0,b1=0,b2=0,b3=0;
#pragma unroll
    for (int c = 0; c < 8; c++) {
        const float4* row = (const float4*)(gf + (size_t)(base + offs[c]) * W_FEAT);
        const float4 fa = __ldg(row + lane);
        const float4 fb = __ldg(row + lane + 32);
        const float wc = w[c];
        a0 = fmaf(wc, fa.x, a0); a1 = fmaf(wc, fa.y, a1);
        a2 = fmaf(wc, fa.z, a2); a3 = fmaf(wc, fa.w, a3);
        b0 = fmaf(wc, fb.x, b0); b1 = fmaf(wc, fb.y, b1);
        b2 = fmaf(wc, fb.z, b2); b3 = fmaf(wc, fb.w, b3);
    }
    float4* frow = (float4*)(out_feat + (size_t)p * W_FEAT);
    frow[lane]      = make_float4(a0*vmask, a1*vmask, a2*vmask, a3*vmask);
    frow[lane + 32] = make_float4(b0*vmask, b1*vmask, b2*vmask, b3*vmask);
}

extern "C" void kernel_launch(void* const* d_in, const int* in_sizes, int n_in,
                              void* d_out, int out_size)
{
    const float* x  = (const float*)d_in[0];
    const float* gv = (const float*)d_in[1];
    const float* gf = (const float*)d_in[2];
    float* out = (float*)d_out;

    const int B = in_sizes[0] / 3;
    float* out_val  = out;        // [B]
    float* out_feat = out + B;    // [B, 256]

    if (B <= MAXB) {
        zero_hist_kernel<<<(NBINS + 255) / 256, 256>>>();
        histo_kernel<<<(B + 255) / 256, 256>>>(x, B);
        scan_kernel<<<1, 1024>>>();
        scatter_kernel<<<(B + 255) / 256, 256>>>(x, B);
        trilerp_l1_kernel<<<NBINS * 2, 512>>>(gv, gf, out_val, out_feat);
    } else {
        const int blocks = (B + 7) / 8;
        trilerp_kernel<<<blocks, 256>>>(x, gv, gf, out_val, out_feat, B);
    }
}